// round 1
// baseline (speedup 1.0000x reference)
#include <cuda_runtime.h>
#include <cuda_bf16.h>

// Weighted AUC, sort-free via fine histogram + tie-exact formula.
// area = sum_i fp_i * (TP_above(bin_i) + 0.5*tp_bin(bin_i));  auc = area/(TP*FP)

#define T_TASKS 16
#define NB 8192                 // prediction bins (uniform [0,1))
#define NPT 2097152             // examples per task
#define N4 (NPT / 4)            // float4 per task
#define CH1 128                 // chunks per task, pass 1
#define CH2 128                 // chunks per task, pass 2
#define THREADS 256

__device__ float  g_hist[T_TASKS * NB];
__device__ float  g_lut[T_TASKS * NB];
__device__ double g_area[T_TASKS];
__device__ double g_fpsum[T_TASKS];
__device__ double g_tpsum[T_TASKS];

__global__ void zero_kernel() {
    int i = blockIdx.x * blockDim.x + threadIdx.x;
    if (i < T_TASKS * NB) g_hist[i] = 0.0f;
    if (i < T_TASKS) { g_area[i] = 0.0; g_fpsum[i] = 0.0; g_tpsum[i] = 0.0; }
}

__global__ void __launch_bounds__(THREADS) pass1_kernel(
    const float4* __restrict__ pp, const float4* __restrict__ ll,
    const float4* __restrict__ ww)
{
    const int task = blockIdx.y;
    const int per  = N4 / CH1;
    const size_t base = (size_t)task * N4 + (size_t)blockIdx.x * per;
    float* hist = g_hist + task * NB;

    for (int i = threadIdx.x; i < per; i += THREADS) {
        float4 pv = __ldg(pp + base + i);
        float4 lv = __ldg(ll + base + i);
        float4 wv = __ldg(ww + base + i);
#define DO_COMP(c)                                                        \
        {                                                                 \
            float tp = wv.c * lv.c;                                       \
            if (tp != 0.0f) {                                             \
                int b = (int)(pv.c * (float)NB);                          \
                b = b < 0 ? 0 : (b > NB - 1 ? NB - 1 : b);                \
                atomicAdd(hist + b, tp);                                  \
            }                                                             \
        }
        DO_COMP(x) DO_COMP(y) DO_COMP(z) DO_COMP(w)
#undef DO_COMP
    }
}

// One block per task. 1024 threads x 8 bins each: double-precision suffix scan.
__global__ void __launch_bounds__(1024) scan_kernel() {
    __shared__ double ssum[1024];
    const int task = blockIdx.x;
    const float* hist = g_hist + (size_t)task * NB;
    float*       lut  = g_lut  + (size_t)task * NB;
    const int t = threadIdx.x;

    float h[8];
    double loc[8];
    double s = 0.0;
#pragma unroll
    for (int j = 7; j >= 0; --j) {
        h[j] = hist[t * 8 + j];
        s += (double)h[j];
        loc[j] = s;                 // inclusive suffix within this thread's 8 bins
    }
    ssum[t] = s;
    __syncthreads();

    // Hillis-Steele inclusive suffix scan over thread totals
    for (int off = 1; off < 1024; off <<= 1) {
        double v = (t + off < 1024) ? ssum[t + off] : 0.0;
        __syncthreads();
        ssum[t] += v;
        __syncthreads();
    }
    const double above = (t + 1 < 1024) ? ssum[t + 1] : 0.0;
#pragma unroll
    for (int j = 0; j < 8; ++j)
        lut[t * 8 + j] = (float)(above + loc[j] - 0.5 * (double)h[j]);

    if (t == 0) g_tpsum[task] = ssum[0];
}

__global__ void __launch_bounds__(THREADS) pass2_kernel(
    const float4* __restrict__ pp, const float4* __restrict__ ll,
    const float4* __restrict__ ww)
{
    __shared__ float  slut[NB];
    __shared__ double sred[2][THREADS / 32];
    const int task = blockIdx.y;

    for (int i = threadIdx.x; i < NB; i += THREADS)
        slut[i] = g_lut[(size_t)task * NB + i];
    __syncthreads();

    const int per  = N4 / CH2;
    const size_t base = (size_t)task * N4 + (size_t)blockIdx.x * per;

    float acc_a = 0.0f, acc_f = 0.0f;
    for (int i = threadIdx.x; i < per; i += THREADS) {
        float4 pv = __ldg(pp + base + i);
        float4 lv = __ldg(ll + base + i);
        float4 wv = __ldg(ww + base + i);
#define DO_COMP(c)                                                        \
        {                                                                 \
            float fp = wv.c * (1.0f - lv.c);                              \
            int b = (int)(pv.c * (float)NB);                              \
            b = b < 0 ? 0 : (b > NB - 1 ? NB - 1 : b);                    \
            float sv = slut[b];                                           \
            acc_a = fmaf(fp, sv, acc_a);                                  \
            acc_f += fp;                                                  \
        }
        DO_COMP(x) DO_COMP(y) DO_COMP(z) DO_COMP(w)
#undef DO_COMP
    }

    double da = (double)acc_a, df = (double)acc_f;
#pragma unroll
    for (int off = 16; off; off >>= 1) {
        da += __shfl_down_sync(0xffffffffu, da, off);
        df += __shfl_down_sync(0xffffffffu, df, off);
    }
    const int warp = threadIdx.x >> 5, lane = threadIdx.x & 31;
    if (lane == 0) { sred[0][warp] = da; sred[1][warp] = df; }
    __syncthreads();
    if (threadIdx.x == 0) {
        double ta = 0.0, tf = 0.0;
#pragma unroll
        for (int k = 0; k < THREADS / 32; ++k) { ta += sred[0][k]; tf += sred[1][k]; }
        atomicAdd(&g_area[task],  ta);
        atomicAdd(&g_fpsum[task], tf);
    }
}

__global__ void finalize_kernel(float* __restrict__ out) {
    const int t = threadIdx.x;
    if (t < T_TASKS) {
        double denom = g_fpsum[t] * g_tpsum[t];
        out[t] = (denom == 0.0) ? 0.5f : (float)(g_area[t] / denom);
    }
}

extern "C" void kernel_launch(void* const* d_in, const int* in_sizes, int n_in,
                              void* d_out, int out_size) {
    // metadata order: n_tasks (scalar), predictions, labels, weights.
    // Be robust to the scalar being absent.
    int off = (n_in >= 4 && in_sizes[0] == 1) ? 1 : 0;
    const float4* p = (const float4*)d_in[off + 0];
    const float4* l = (const float4*)d_in[off + 1];
    const float4* w = (const float4*)d_in[off + 2];

    zero_kernel<<<(T_TASKS * NB + 255) / 256, 256>>>();

    dim3 g1(CH1, T_TASKS);
    pass1_kernel<<<g1, THREADS>>>(p, l, w);

    scan_kernel<<<T_TASKS, 1024>>>();

    dim3 g2(CH2, T_TASKS);
    pass2_kernel<<<g2, THREADS>>>(p, l, w);

    finalize_kernel<<<1, 32>>>((float*)d_out);
}

// round 3
// speedup vs baseline: 2.6816x; 2.6816x over previous
#include <cuda_runtime.h>
#include <cuda_bf16.h>

// Weighted AUC in ONE data pass.
// Labels are exactly 0/1, so each element adds w to either tp_hist[bin] or
// fp_hist[bin]. Then area = sum_b fp[b] * (TP_above(b) + 0.5*tp[b]) and
// auc = area / (TP_total * FP_total), all from the histograms alone.

#define T_TASKS 16
#define NB 4096                // prediction bins, uniform [0,1)
#define NPT 2097152            // examples per task
#define N4 (NPT / 4)
#define CHUNKS 16              // blocks per task
#define THREADS 1024

// Layout: per task [tp_hist(NB)][fp_hist(NB)]
__device__ float g_hist[T_TASKS * 2 * NB];

__global__ void zero_kernel() {
    int i = blockIdx.x * blockDim.x + threadIdx.x;
    if (i < T_TASKS * 2 * NB) g_hist[i] = 0.0f;
}

__global__ void __launch_bounds__(THREADS) hist_kernel(
    const float4* __restrict__ pp, const float4* __restrict__ ll,
    const float4* __restrict__ ww)
{
    __shared__ float sh[2 * NB];   // 32 KB: [tp NB][fp NB]
    const int task = blockIdx.y;
    const int tid  = threadIdx.x;

    for (int i = tid; i < 2 * NB; i += THREADS) sh[i] = 0.0f;
    __syncthreads();

    const int per4 = N4 / CHUNKS;                      // 32768 float4 per block
    const size_t base = (size_t)task * N4 + (size_t)blockIdx.x * per4;

    for (int i = tid; i < per4; i += THREADS) {
        float4 pv = __ldg(pp + base + i);
        float4 lv = __ldg(ll + base + i);
        float4 wv = __ldg(ww + base + i);
#define DO_COMP(c)                                                        \
        {                                                                 \
            int b = (int)(pv.c * (float)NB);                              \
            b = b < 0 ? 0 : (b > NB - 1 ? NB - 1 : b);                    \
            int off = b + ((lv.c == 0.0f) ? NB : 0);                      \
            atomicAdd(sh + off, wv.c);                                    \
        }
        DO_COMP(x) DO_COMP(y) DO_COMP(z) DO_COMP(w)
#undef DO_COMP
    }
    __syncthreads();

    float* gh = g_hist + (size_t)task * 2 * NB;
    for (int i = tid; i < 2 * NB; i += THREADS) {
        float v = sh[i];
        if (v != 0.0f) atomicAdd(gh + i, v);
    }
}

// One block per task: double-precision suffix scan of tp_hist + area + final AUC.
__global__ void __launch_bounds__(1024) finalize_kernel(float* __restrict__ out) {
    __shared__ double ssum[1024];
    __shared__ double sred[2][32];
    const int task = blockIdx.x;
    const float* tp = g_hist + (size_t)task * 2 * NB;
    const float* fp = tp + NB;
    const int t = threadIdx.x;                 // 4 bins per thread

    float  th[4];
    double loc[4];
    double s = 0.0;
#pragma unroll
    for (int j = 3; j >= 0; --j) {
        th[j] = tp[t * 4 + j];
        s += (double)th[j];
        loc[j] = s;                            // inclusive suffix within thread
    }
    ssum[t] = s;
    __syncthreads();

    // Hillis-Steele inclusive suffix scan over thread totals
    for (int off = 1; off < 1024; off <<= 1) {
        double v = (t + off < 1024) ? ssum[t + off] : 0.0;
        __syncthreads();
        ssum[t] += v;
        __syncthreads();
    }
    const double above = (t + 1 < 1024) ? ssum[t + 1] : 0.0;

    double a = 0.0, f = 0.0;
#pragma unroll
    for (int j = 0; j < 4; ++j) {
        double fv  = (double)fp[t * 4 + j];
        double lut = above + loc[j] - 0.5 * (double)th[j];
        a += fv * lut;
        f += fv;
    }

#pragma unroll
    for (int off = 16; off; off >>= 1) {
        a += __shfl_down_sync(0xffffffffu, a, off);
        f += __shfl_down_sync(0xffffffffu, f, off);
    }
    const int warp = t >> 5, lane = t & 31;
    if (lane == 0) { sred[0][warp] = a; sred[1][warp] = f; }
    __syncthreads();
    if (t == 0) {
        double ta = 0.0, tf = 0.0;
#pragma unroll
        for (int k = 0; k < 32; ++k) { ta += sred[0][k]; tf += sred[1][k]; }
        double tp_total = ssum[0];
        double denom = tf * tp_total;
        out[task] = (denom == 0.0) ? 0.5f : (float)(ta / denom);
    }
}

extern "C" void kernel_launch(void* const* d_in, const int* in_sizes, int n_in,
                              void* d_out, int out_size) {
    int off = (n_in >= 4 && in_sizes[0] == 1) ? 1 : 0;
    const float4* p = (const float4*)d_in[off + 0];
    const float4* l = (const float4*)d_in[off + 1];
    const float4* w = (const float4*)d_in[off + 2];

    zero_kernel<<<(T_TASKS * 2 * NB + 255) / 256, 256>>>();

    dim3 g(CHUNKS, T_TASKS);
    hist_kernel<<<g, THREADS>>>(p, l, w);

    finalize_kernel<<<T_TASKS, 1024>>>((float*)d_out);
}

// round 4
// speedup vs baseline: 2.8243x; 1.0532x over previous
#include <cuda_runtime.h>
#include <cuda_bf16.h>

// Weighted AUC in ONE data pass.
// Labels are exactly 0/1, so each element adds w to either tp_hist[bin] or
// fp_hist[bin]. Then area = sum_b fp[b] * (TP_above(b) + 0.5*tp[b]) and
// auc = area / (TP_total * FP_total), all from the histograms alone.

#define T_TASKS 16
#define NB 4096                // prediction bins, uniform [0,1)
#define NPT 2097152            // examples per task
#define N4 (NPT / 4)           // 524288 float4 per task
#define CHUNKS 37              // 16*37 = 592 = 4 blocks per SM exactly (148 SMs)
#define PER_CHUNK 14171        // ceil(N4 / 37)
#define THREADS 512

// Layout: per task [tp_hist(NB)][fp_hist(NB)]
__device__ float g_hist[T_TASKS * 2 * NB];

__global__ void zero_kernel() {
    int i = blockIdx.x * blockDim.x + threadIdx.x;
    float4* p = (float4*)g_hist;
    if (i < T_TASKS * 2 * NB / 4) p[i] = make_float4(0.f, 0.f, 0.f, 0.f);
}

__global__ void __launch_bounds__(THREADS, 4) hist_kernel(
    const float4* __restrict__ pp, const float4* __restrict__ ll,
    const float4* __restrict__ ww)
{
    __shared__ float sh[2 * NB];   // 32 KB: [tp NB][fp NB]
    const int task = blockIdx.y;
    const int tid  = threadIdx.x;

    for (int i = tid; i < 2 * NB; i += THREADS) sh[i] = 0.0f;
    __syncthreads();

    const int start = blockIdx.x * PER_CHUNK;
    const int end   = (start + PER_CHUNK < N4) ? start + PER_CHUNK : N4;
    const int base  = task * N4 + start;          // < 2^23, fits int
    const int cnt   = end - start;

    for (int i = tid; i < cnt; i += THREADS) {
        float4 pv = __ldg(pp + base + i);
        float4 lv = __ldg(ll + base + i);
        float4 wv = __ldg(ww + base + i);
#define DO_COMP(c)                                                        \
        {                                                                 \
            int b = (int)(pv.c * (float)NB);                              \
            b = b < 0 ? 0 : (b > NB - 1 ? NB - 1 : b);                    \
            int off = b + ((lv.c == 0.0f) ? NB : 0);                      \
            atomicAdd(sh + off, wv.c);                                    \
        }
        DO_COMP(x) DO_COMP(y) DO_COMP(z) DO_COMP(w)
#undef DO_COMP
    }
    __syncthreads();

    float* gh = g_hist + task * 2 * NB;
    for (int i = tid; i < 2 * NB; i += THREADS) {
        float v = sh[i];
        if (v != 0.0f) atomicAdd(gh + i, v);
    }
}

// One block per task: double-precision suffix scan of tp_hist + area + final AUC.
__global__ void __launch_bounds__(1024) finalize_kernel(float* __restrict__ out) {
    __shared__ double ssum[1024];
    __shared__ double sred[2][32];
    const int task = blockIdx.x;
    const float* tp = g_hist + (size_t)task * 2 * NB;
    const float* fp = tp + NB;
    const int t = threadIdx.x;                 // 4 bins per thread

    float  th[4];
    double loc[4];
    double s = 0.0;
#pragma unroll
    for (int j = 3; j >= 0; --j) {
        th[j] = tp[t * 4 + j];
        s += (double)th[j];
        loc[j] = s;                            // inclusive suffix within thread
    }
    ssum[t] = s;
    __syncthreads();

    // Hillis-Steele inclusive suffix scan over thread totals
    for (int off = 1; off < 1024; off <<= 1) {
        double v = (t + off < 1024) ? ssum[t + off] : 0.0;
        __syncthreads();
        ssum[t] += v;
        __syncthreads();
    }
    const double above = (t + 1 < 1024) ? ssum[t + 1] : 0.0;

    double a = 0.0, f = 0.0;
#pragma unroll
    for (int j = 0; j < 4; ++j) {
        double fv  = (double)fp[t * 4 + j];
        double lut = above + loc[j] - 0.5 * (double)th[j];
        a += fv * lut;
        f += fv;
    }

#pragma unroll
    for (int off = 16; off; off >>= 1) {
        a += __shfl_down_sync(0xffffffffu, a, off);
        f += __shfl_down_sync(0xffffffffu, f, off);
    }
    const int warp = t >> 5, lane = t & 31;
    if (lane == 0) { sred[0][warp] = a; sred[1][warp] = f; }
    __syncthreads();
    if (t == 0) {
        double ta = 0.0, tf = 0.0;
#pragma unroll
        for (int k = 0; k < 32; ++k) { ta += sred[0][k]; tf += sred[1][k]; }
        double tp_total = ssum[0];
        double denom = tf * tp_total;
        out[task] = (denom == 0.0) ? 0.5f : (float)(ta / denom);
    }
}

extern "C" void kernel_launch(void* const* d_in, const int* in_sizes, int n_in,
                              void* d_out, int out_size) {
    int off = (n_in >= 4 && in_sizes[0] == 1) ? 1 : 0;
    const float4* p = (const float4*)d_in[off + 0];
    const float4* l = (const float4*)d_in[off + 1];
    const float4* w = (const float4*)d_in[off + 2];

    zero_kernel<<<(T_TASKS * 2 * NB / 4 + 255) / 256, 256>>>();

    dim3 g(CHUNKS, T_TASKS);
    hist_kernel<<<g, THREADS>>>(p, l, w);

    finalize_kernel<<<T_TASKS, 1024>>>((float*)d_out);
}

// round 5
// speedup vs baseline: 2.8681x; 1.0155x over previous
#include <cuda_runtime.h>
#include <cuda_bf16.h>

// Weighted AUC, single fused kernel.
// Labels are exactly 0/1: each element adds w to tp_hist[bin] or fp_hist[bin].
// area = sum_b fp[b]*(TP_above(b) + 0.5*tp[b]);  auc = area/(TP_tot*FP_tot).
// Per-task last-finishing block does the scan+AUC and restores global state
// (g_hist zeros, counter zero) so every call/graph-replay is identical.

#define T_TASKS 16
#define NB 4096                // prediction bins, uniform [0,1)
#define NPT 2097152
#define N4 (NPT / 4)           // 524288 float4 per task
#define CHUNKS 37              // 16*37 = 592 blocks = 4 per SM on 148 SMs
#define PER_CHUNK 14171        // ceil(N4/37)
#define THREADS 512
#define BINS_PT (NB / THREADS) // 8 bins per thread in finalize path

__device__ float        g_hist[T_TASKS * 2 * NB];   // zero-init at load
__device__ unsigned int g_count[T_TASKS];           // zero-init at load

__global__ void __launch_bounds__(THREADS, 4) auc_kernel(
    const float4* __restrict__ pp, const float4* __restrict__ ll,
    const float4* __restrict__ ww, float* __restrict__ out)
{
    __shared__ __align__(16) float sh[2 * NB];   // 32 KB: [tp NB][fp NB]
    const int task = blockIdx.y;
    const int t    = threadIdx.x;

    for (int i = t; i < 2 * NB; i += THREADS) sh[i] = 0.0f;
    __syncthreads();

    // ---- histogram phase ----
    {
        const int start = blockIdx.x * PER_CHUNK;
        const int end   = (start + PER_CHUNK < N4) ? start + PER_CHUNK : N4;
        const int base  = task * N4 + start;
        const int cnt   = end - start;

#pragma unroll 2
        for (int i = t; i < cnt; i += THREADS) {
            float4 pv = __ldcs(pp + base + i);
            float4 lv = __ldcs(ll + base + i);
            float4 wv = __ldcs(ww + base + i);
#define DO_COMP(c)                                                        \
            {                                                             \
                int b = (int)(pv.c * (float)NB);                          \
                b = b > NB - 1 ? NB - 1 : b;                              \
                int off = b + ((lv.c == 0.0f) ? NB : 0);                  \
                atomicAdd(sh + off, wv.c);                                \
            }
            DO_COMP(x) DO_COMP(y) DO_COMP(z) DO_COMP(w)
#undef DO_COMP
        }
    }
    __syncthreads();

    // ---- flush to global ----
    float* gh = g_hist + task * 2 * NB;
    for (int i = t; i < 2 * NB; i += THREADS) {
        float v = sh[i];
        if (v != 0.0f) atomicAdd(gh + i, v);
    }
    __threadfence();
    __syncthreads();

    // ---- elect last block per task ----
    __shared__ unsigned s_last;
    if (t == 0) s_last = atomicAdd(&g_count[task], 1u);
    __syncthreads();
    if (s_last != CHUNKS - 1) return;
    __threadfence();   // acquire: see all other blocks' hist atomics

    // ---- finalize (this block only): suffix scan + area + auc ----
    float* fsum = sh;                 // reuse smem (512 floats)
    float  th[BINS_PT], loc[BINS_PT];
    float  s = 0.0f;
#pragma unroll
    for (int j = BINS_PT - 1; j >= 0; --j) {
        th[j] = gh[t * BINS_PT + j];
        s += th[j];
        loc[j] = s;                   // inclusive suffix within thread's bins
    }
    fsum[t] = s;
    __syncthreads();

    // Hillis-Steele inclusive suffix scan over 512 thread totals
    for (int off = 1; off < THREADS; off <<= 1) {
        float v = (t + off < THREADS) ? fsum[t + off] : 0.0f;
        __syncthreads();
        fsum[t] += v;
        __syncthreads();
    }
    const float above = (t + 1 < THREADS) ? fsum[t + 1] : 0.0f;
    const float tp_total = fsum[0];
    __syncthreads();

    double a = 0.0, f = 0.0;
#pragma unroll
    for (int j = 0; j < BINS_PT; ++j) {
        float fv  = gh[NB + t * BINS_PT + j];
        float lut = above + loc[j] - 0.5f * th[j];
        a += (double)fv * (double)lut;
        f += (double)fv;
    }

#pragma unroll
    for (int off = 16; off; off >>= 1) {
        a += __shfl_down_sync(0xffffffffu, a, off);
        f += __shfl_down_sync(0xffffffffu, f, off);
    }
    double* sred = (double*)sh;       // reuse smem again (32 doubles)
    const int warp = t >> 5, lane = t & 31;
    __syncthreads();
    if (lane == 0) { sred[warp] = a; sred[16 + warp] = f; }
    __syncthreads();

    if (t == 0) {
        double ta = 0.0, tf = 0.0;
#pragma unroll
        for (int k = 0; k < THREADS / 32; ++k) { ta += sred[k]; tf += sred[16 + k]; }
        double denom = tf * (double)tp_total;
        out[task] = (denom == 0.0) ? 0.5f : (float)(ta / denom);
        g_count[task] = 0u;           // restore invariant for next call
    }

    // restore g_hist zeros for next call / replay
    for (int i = t; i < 2 * NB; i += THREADS) gh[i] = 0.0f;
}

extern "C" void kernel_launch(void* const* d_in, const int* in_sizes, int n_in,
                              void* d_out, int out_size) {
    int off = (n_in >= 4 && in_sizes[0] == 1) ? 1 : 0;
    const float4* p = (const float4*)d_in[off + 0];
    const float4* l = (const float4*)d_in[off + 1];
    const float4* w = (const float4*)d_in[off + 2];

    dim3 g(CHUNKS, T_TASKS);
    auc_kernel<<<g, THREADS>>>(p, l, w, (float*)d_out);
}